// round 12
// baseline (speedup 1.0000x reference)
#include <cuda_runtime.h>
#include <math.h>

#define GN     6
#define GC     7       // clamped grid side (row/col 6 = trash)
#define NROW   (GC*GC) // 49 histogram rows
#define NCELL  36
#define HID    128
#define NT     64      // threads per block (pair kernel)
#define APB    (2*NT)  // agents per block = 128 (2 per thread)
#define SEG    64      // j-segments -> grid 4096 when N=8192
#define TJ     128     // j tile size; counts per segment <= 128 -> fit in u8
#define MAXN   8192
#define BI     16      // rows per block in fused epilogue (512 blocks at N=8192)

// Packed partials: [seg][cell][k] u16 = (countA:u8) | (countB:u8 << 8),
// where pair k -> agents iA = (k>>6)*128 + (k&63), iB = iA + 64.
__device__ unsigned short g_part[SEG * NCELL * (MAXN / 2)];
// Reduced occupancy for the generic-N fallback path: [cell][i]
__device__ float g_occ[NCELL * MAXN];

__device__ __forceinline__ unsigned long long addf32x2(unsigned long long a,
                                                       unsigned long long b) {
    unsigned long long r;
    asm("add.rn.f32x2 %0, %1, %2;" : "=l"(r) : "l"(a), "l"(b));
    return r;
}
__device__ __forceinline__ unsigned long long packf2(float lo, float hi) {
    unsigned long long r;
    asm("mov.b64 %0, {%1, %2};" : "=l"(r) : "f"(lo), "f"(hi));
    return r;
}

// pj holds packed (2xj+3, 2yj+3); ni holds packed (-2xi, -2yi). One FADD2 joins
// them (per-lane RN identical to scalar FADD). Clamp-grid trash: min(unsigned,6)
// sends every invalid coordinate (negative -> unsigned-huge, >=6, or saturated
// F2I from the +1e30 sentinels) to row/col 6. Histogram u32, conflict-free
// (bank = tid%32): agent A at bit 0, agent B at bit 16; counts <= 128.
__device__ __forceinline__ void bump(unsigned* occ, int tid,
                                     unsigned long long pj, unsigned long long ni,
                                     unsigned inc) {
    const unsigned long long r = addf32x2(pj, ni);
    float fx, fy;
    asm("mov.b64 {%0, %1}, %2;" : "=f"(fx), "=f"(fy) : "l"(r));
    unsigned ix = umin((unsigned)__float2int_rd(fx), (unsigned)(GC - 1));
    unsigned iy = umin((unsigned)__float2int_rd(fy), (unsigned)(GC - 1));
    occ[(ix * GC + iy) * NT + tid] += inc;
}

template<bool EXACT>
__global__ __launch_bounds__(NT, 16)
void occ_pair_kernel(const float2* __restrict__ obs, int N, int NP) {
    __shared__ __align__(16) float2 tile[TJ];    // holds (2*xj+3, 2*yj+3)
    __shared__ unsigned occ[NROW * NT];

    const int tid = threadIdx.x;
    const int iA  = blockIdx.x * APB + tid;
    const int iB  = iA + NT;
    const int seg = blockIdx.y;
    const int JS  = EXACT ? (MAXN / SEG) : ((N + SEG - 1) / SEG);
    const int j0  = seg * JS;
    const int j1  = EXACT ? (j0 + JS) : min(j0 + JS, N);

    // Hold packed -2*x_i (exact: *2 exact, negate exact). Invalid -> +1e30.
    float nxA = 1e30f, nyA = 1e30f, nxB = 1e30f, nyB = 1e30f;
    if (iA < N) {
        float2 p = obs[iA];
        if (!isnan(p.x) && !isnan(p.y)) { nxA = -2.0f * p.x; nyA = -2.0f * p.y; }
    }
    if (iB < N) {
        float2 p = obs[iB];
        if (!isnan(p.x) && !isnan(p.y)) { nxB = -2.0f * p.x; nyB = -2.0f * p.y; }
    }
    const unsigned long long nA = packf2(nxA, nyA);
    const unsigned long long nB = packf2(nxB, nyB);

    #pragma unroll
    for (int c = 0; c < NROW; c++) occ[c * NT + tid] = 0;
    __syncthreads();

    for (int jb = j0; jb < j1; jb += TJ) {
        const int nj = EXACT ? TJ : min(TJ, j1 - jb);
        for (int t = tid; t < nj; t += NT) {
            float2 p = obs[jb + t];
            float2 v;
            if (isnan(p.x) || isnan(p.y)) { v.x = 1e30f; v.y = 1e30f; }
            else { v.x = fmaf(p.x, 2.0f, 3.0f); v.y = fmaf(p.y, 2.0f, 3.0f); }
            tile[t] = v;
        }
        __syncthreads();

        // Two packed j's per LDS.128 broadcast; one FADD2 per pair.
        const ulonglong2* t2 = (const ulonglong2*)tile;
        const int nj2 = nj >> 1;
        #pragma unroll 4
        for (int jj = 0; jj < nj2; jj++) {
            const ulonglong2 q = t2[jj];
            bump(occ, tid, q.x, nA, 1u);
            bump(occ, tid, q.x, nB, 1u << 16);
            bump(occ, tid, q.y, nA, 1u);
            bump(occ, tid, q.y, nB, 1u << 16);
        }
        if (!EXACT && (nj & 1)) {
            const unsigned long long q =
                *reinterpret_cast<const unsigned long long*>(&tile[nj - 1]);
            bump(occ, tid, q, nA, 1u);
            bump(occ, tid, q, nB, 1u << 16);
        }
        __syncthreads();
    }

    // Store 36 real cells packed: (A count u8) | (B count u8 << 8). OOB agents
    // contributed only to clamp rows, so their real cells are 0 -> safe.
    const int k = blockIdx.x * NT + tid;
    #pragma unroll
    for (int c = 0; c < NCELL; c++) {
        const int row = (c / GN) * GC + (c % GN);
        const unsigned v = occ[row * NT + tid];
        g_part[(seg * NCELL + c) * NP + k] =
            (unsigned short)((v & 0xFFu) | ((v >> 8) & 0xFF00u));
    }
}

// Fused reduce + [BI,36]x[36,128] GEMM (N % 128 == 0 path). 512 blocks at
// N=8192: each block reduces its own 16 agents' partials directly from g_part
// (288 tasks x 64 independent u32 loads) into smem, then does the GEMM.
__global__ __launch_bounds__(256)
void occ_fused_kernel(const float2* __restrict__ obs,
                      const float*  __restrict__ W,
                      const float*  __restrict__ b,
                      float*        __restrict__ out, int N, int NP) {
    __shared__ float sW[HID * 37];                   // stride 37: conflict-free
    __shared__ __align__(16) float occ_s[BI][40];    // row stride 40: float4-aligned
    __shared__ float sself[BI];

    const int tid = threadIdx.x;
    const int i0  = blockIdx.x * BI;

    // Stage W coalesced.
    for (int idx = tid; idx < HID * NCELL; idx += 256) {
        const int h = idx / NCELL;
        sW[h * 37 + (idx - h * NCELL)] = W[idx];
    }

    // Reduce phase: agents [i0, i0+16) live in one byte-lane (A if i0%128<64
    // else B) of 16 consecutive pair-slots starting at k0.
    const int ib    = i0 >> 7;
    const int rem   = i0 & 127;
    const int shift = (rem < 64) ? 0 : 8;
    const int k0    = ib * 64 + (rem & 63);
    const unsigned* gp = reinterpret_cast<const unsigned*>(g_part);
    const int strideU  = (NCELL * NP) >> 1;          // u32 stride per segment

    for (int t = tid; t < NCELL * (BI / 2); t += 256) {
        const int c  = t >> 3;                       // cell
        const int sp = t & 7;                        // slot pair
        const unsigned* base = gp + ((c * NP + k0 + sp * 2) >> 1);
        unsigned acc = 0u;                           // halfword sums <= 8192
        #pragma unroll 16
        for (int sg = 0; sg < SEG; sg++)
            acc = __vadd2(acc, (base[sg * strideU] >> shift) & 0x00FF00FFu);
        occ_s[sp * 2 + 0][c] = (float)(acc & 0xFFFFu);
        occ_s[sp * 2 + 1][c] = (float)(acc >> 16);
    }
    if (tid < BI) {
        const int i = i0 + tid;
        float v = 0.f;
        if (i < N) {
            const float2 p = obs[i];
            if (!isnan(p.x) && !isnan(p.y)) v = 1.f;
        }
        sself[tid] = v;
    }
    __syncthreads();

    // GEMM phase.
    const int h = tid & (HID - 1);
    float w[NCELL];
    #pragma unroll
    for (int c = 0; c < NCELL; c++) w[c] = sW[h * 37 + c];
    const float bias = b[h];

    const int il0 = (tid >> 7) * (BI / 2);
    #pragma unroll
    for (int r = 0; r < BI / 2; r++) {
        const int il = il0 + r;
        const int i  = i0 + il;
        if (i >= N) break;
        // Self-pair was counted at cell 21 iff agent i is finite; remove it.
        float acc = fmaf(-sself[il], w[21], bias);
        const float4* row = (const float4*)&occ_s[il][0];
        #pragma unroll
        for (int c4 = 0; c4 < 9; c4++) {
            const float4 v = row[c4];     // broadcast LDS.128
            acc = fmaf(v.x, w[c4 * 4 + 0], acc);
            acc = fmaf(v.y, w[c4 * 4 + 1], acc);
            acc = fmaf(v.z, w[c4 * 4 + 2], acc);
            acc = fmaf(v.w, w[c4 * 4 + 3], acc);
        }
        out[i * HID + h] = acc;
    }
}

// ---- Generic-N fallback path -------------------------------------------
__global__ __launch_bounds__(256)
void occ_reduce_generic(int N, int NP) {
    const int t = blockIdx.x * 256 + threadIdx.x;
    if (t >= NCELL * NP) return;
    const int c = t / NP;
    const int k = t - c * NP;
    unsigned sA = 0, sB = 0;
    #pragma unroll 8
    for (int sg = 0; sg < SEG; sg++) {
        const unsigned v = g_part[(sg * NCELL + c) * NP + k];
        sA += v & 0xFFu;
        sB += (v >> 8) & 0xFFu;
    }
    const int iA = (k >> 6) * 128 + (k & 63);
    const int iB = iA + 64;
    if (iA < N) g_occ[c * N + iA] = (float)sA;
    if (iB < N) g_occ[c * N + iB] = (float)sB;
}

__global__ __launch_bounds__(256)
void occ_gemm_kernel(const float2* __restrict__ obs,
                     const float*  __restrict__ W,
                     const float*  __restrict__ b,
                     float*        __restrict__ out, int N) {
    __shared__ float sW[HID * 37];
    __shared__ __align__(16) float occ_s[BI][40];
    __shared__ float sself[BI];

    const int tid = threadIdx.x;
    const int i0  = blockIdx.x * BI;

    for (int idx = tid; idx < HID * NCELL; idx += 256) {
        const int h = idx / NCELL;
        sW[h * 37 + (idx - h * NCELL)] = W[idx];
    }
    for (int idx = tid; idx < NCELL * BI; idx += 256) {
        const int c = idx >> 4, l = idx & (BI - 1);
        const int i = i0 + l;
        occ_s[l][c] = (i < N) ? g_occ[c * N + i] : 0.f;
    }
    if (tid < BI) {
        const int i = i0 + tid;
        float v = 0.f;
        if (i < N) {
            const float2 p = obs[i];
            if (!isnan(p.x) && !isnan(p.y)) v = 1.f;
        }
        sself[tid] = v;
    }
    __syncthreads();

    const int h = tid & (HID - 1);
    float w[NCELL];
    #pragma unroll
    for (int c = 0; c < NCELL; c++) w[c] = sW[h * 37 + c];
    const float bias = b[h];

    const int il0 = (tid >> 7) * (BI / 2);
    #pragma unroll
    for (int r = 0; r < BI / 2; r++) {
        const int il = il0 + r;
        const int i  = i0 + il;
        if (i >= N) break;
        float acc = fmaf(-sself[il], w[21], bias);
        const float4* row = (const float4*)&occ_s[il][0];
        #pragma unroll
        for (int c4 = 0; c4 < 9; c4++) {
            const float4 v = row[c4];
            acc = fmaf(v.x, w[c4 * 4 + 0], acc);
            acc = fmaf(v.y, w[c4 * 4 + 1], acc);
            acc = fmaf(v.z, w[c4 * 4 + 2], acc);
            acc = fmaf(v.w, w[c4 * 4 + 3], acc);
        }
        out[i * HID + h] = acc;
    }
}

extern "C" void kernel_launch(void* const* d_in, const int* in_sizes, int n_in,
                              void* d_out, int out_size) {
    const float2* obs = (const float2*)d_in[0];
    const float*  W   = (const float*)d_in[1];
    const float*  b   = (const float*)d_in[2];
    float*        out = (float*)d_out;
    const int N  = in_sizes[0] / 2;
    const int GX = (N + APB - 1) / APB;
    const int NP = GX * NT;                // pair slots

    dim3 g1(GX, SEG);
    if (N == MAXN) occ_pair_kernel<true><<<g1, NT>>>(obs, N, NP);
    else           occ_pair_kernel<false><<<g1, NT>>>(obs, N, NP);

    if ((N & 127) == 0) {
        occ_fused_kernel<<<N / BI, 256>>>(obs, W, b, out, N, NP);
    } else {
        const int rthreads = NCELL * NP;
        occ_reduce_generic<<<(rthreads + 255) / 256, 256>>>(N, NP);
        occ_gemm_kernel<<<(N + BI - 1) / BI, 256>>>(obs, W, b, out, N);
    }
}

// round 13
// speedup vs baseline: 1.0888x; 1.0888x over previous
#include <cuda_runtime.h>
#include <math.h>

#define GN     6
#define GC     7       // clamped grid side (row/col 6 = trash)
#define NROW   (GC*GC) // 49 histogram rows
#define NCELL  36
#define HID    128
#define NT     64      // threads per block (pair kernel)
#define APB    (2*NT)  // agents per block = 128 (2 per thread)
#define SEG    64      // j-segments -> grid 4096 when N=8192
#define TJ     128     // j tile size; counts per segment <= 128 -> fit in u8
#define MAXN   8192
#define BI     16      // rows per block in GEMM kernel (512 blocks at N=8192)

// Packed partials: [seg][cell][k] u16 = (countA:u8) | (countB:u8 << 8),
// where pair k -> agents iA = (k>>6)*128 + (k&63), iB = iA + 64.
__device__ unsigned short g_part[SEG * NCELL * (MAXN / 2)];
// Reduced occupancy, transposed float: [cell][i]
__device__ float g_occ[NCELL * MAXN];

__device__ __forceinline__ unsigned long long addf32x2(unsigned long long a,
                                                       unsigned long long b) {
    unsigned long long r;
    asm("add.rn.f32x2 %0, %1, %2;" : "=l"(r) : "l"(a), "l"(b));
    return r;
}
__device__ __forceinline__ unsigned long long packf2(float lo, float hi) {
    unsigned long long r;
    asm("mov.b64 %0, {%1, %2};" : "=l"(r) : "f"(lo), "f"(hi));
    return r;
}

// pj holds packed (2xj+3, 2yj+3); ni holds packed (-2xi, -2yi). One FADD2 joins
// them (per-lane RN identical to scalar FADD). Clamp-grid trash: min(unsigned,6)
// sends every invalid coordinate (negative -> unsigned-huge, >=6, or saturated
// F2I from the +1e30 sentinels) to row/col 6. Histogram u32, conflict-free
// (bank = tid%32): agent A at bit 0, agent B at bit 16; counts <= 128.
__device__ __forceinline__ void bump(unsigned* occ, int tid,
                                     unsigned long long pj, unsigned long long ni,
                                     unsigned inc) {
    const unsigned long long r = addf32x2(pj, ni);
    float fx, fy;
    asm("mov.b64 {%0, %1}, %2;" : "=f"(fx), "=f"(fy) : "l"(r));
    unsigned ix = umin((unsigned)__float2int_rd(fx), (unsigned)(GC - 1));
    unsigned iy = umin((unsigned)__float2int_rd(fy), (unsigned)(GC - 1));
    occ[(ix * GC + iy) * NT + tid] += inc;
}

template<bool EXACT>
__global__ __launch_bounds__(NT, 16)
void occ_pair_kernel(const float2* __restrict__ obs, int N, int NP) {
    __shared__ __align__(16) float2 tile[TJ];    // holds (2*xj+3, 2*yj+3)
    __shared__ unsigned occ[NROW * NT];

    const int tid = threadIdx.x;
    const int iA  = blockIdx.x * APB + tid;
    const int iB  = iA + NT;
    const int seg = blockIdx.y;
    const int JS  = EXACT ? (MAXN / SEG) : ((N + SEG - 1) / SEG);
    const int j0  = seg * JS;
    const int j1  = EXACT ? (j0 + JS) : min(j0 + JS, N);

    // Hold packed -2*x_i (exact: *2 exact, negate exact). Invalid -> +1e30.
    float nxA = 1e30f, nyA = 1e30f, nxB = 1e30f, nyB = 1e30f;
    if (iA < N) {
        float2 p = obs[iA];
        if (!isnan(p.x) && !isnan(p.y)) { nxA = -2.0f * p.x; nyA = -2.0f * p.y; }
    }
    if (iB < N) {
        float2 p = obs[iB];
        if (!isnan(p.x) && !isnan(p.y)) { nxB = -2.0f * p.x; nyB = -2.0f * p.y; }
    }
    const unsigned long long nA = packf2(nxA, nyA);
    const unsigned long long nB = packf2(nxB, nyB);

    #pragma unroll
    for (int c = 0; c < NROW; c++) occ[c * NT + tid] = 0;
    __syncthreads();

    for (int jb = j0; jb < j1; jb += TJ) {
        const int nj = EXACT ? TJ : min(TJ, j1 - jb);
        for (int t = tid; t < nj; t += NT) {
            float2 p = obs[jb + t];
            float2 v;
            if (isnan(p.x) || isnan(p.y)) { v.x = 1e30f; v.y = 1e30f; }
            else { v.x = fmaf(p.x, 2.0f, 3.0f); v.y = fmaf(p.y, 2.0f, 3.0f); }
            tile[t] = v;
        }
        __syncthreads();

        // Two packed j's per LDS.128 broadcast; one FADD2 per pair.
        const ulonglong2* t2 = (const ulonglong2*)tile;
        const int nj2 = nj >> 1;
        #pragma unroll 4
        for (int jj = 0; jj < nj2; jj++) {
            const ulonglong2 q = t2[jj];
            bump(occ, tid, q.x, nA, 1u);
            bump(occ, tid, q.x, nB, 1u << 16);
            bump(occ, tid, q.y, nA, 1u);
            bump(occ, tid, q.y, nB, 1u << 16);
        }
        if (!EXACT && (nj & 1)) {
            const unsigned long long q =
                *reinterpret_cast<const unsigned long long*>(&tile[nj - 1]);
            bump(occ, tid, q, nA, 1u);
            bump(occ, tid, q, nB, 1u << 16);
        }
        __syncthreads();
    }

    // Store 36 real cells packed: (A count u8) | (B count u8 << 8). OOB agents
    // contributed only to clamp rows, so their real cells are 0 -> safe.
    const int k = blockIdx.x * NT + tid;
    #pragma unroll
    for (int c = 0; c < NCELL; c++) {
        const int row = (c / GN) * GC + (c % GN);
        const unsigned v = occ[row * NT + tid];
        g_part[(seg * NCELL + c) * NP + k] =
            (unsigned short)((v & 0xFFu) | ((v >> 8) & 0xFF00u));
    }
}

// Vector reduction (N % 128 == 0): one thread per (cell, 2 pair-slots).
// 73728 threads at N=8192 -> latency fully hidden; u32 load = 2 packed slots.
// Byte layout of v: [A0, B0, A1, B1] -> A halfwords via & 0x00FF00FF,
// B via (>>8) & 0x00FF00FF; vadd2 halfword sums <= SEG*TJ = 8192, no overflow.
__global__ __launch_bounds__(128)
void occ_reduce_kernel(int N, int NP) {
    const int nK2 = NP >> 1;
    const int t   = blockIdx.x * 128 + threadIdx.x;
    if (t >= NCELL * nK2) return;
    const int c  = t / nK2;
    const int k0 = (t - c * nK2) * 2;

    unsigned aA = 0u, aB = 0u;
    const unsigned* base = reinterpret_cast<const unsigned*>(g_part) + (c * NP + k0) / 2;
    #pragma unroll 16
    for (int sg = 0; sg < SEG; sg++) {
        const unsigned v = base[sg * (NCELL * NP / 2)];
        aA = __vadd2(aA, v & 0x00FF00FFu);
        aB = __vadd2(aB, (v >> 8) & 0x00FF00FFu);
    }
    // Agents: iA0, iA0+1 (consecutive) and iA0+64, iA0+65.
    const int iA0 = (k0 >> 6) * 128 + (k0 & 63);
    float2 fa, fb;
    fa.x = (float)(aA & 0xFFFFu); fa.y = (float)(aA >> 16);
    fb.x = (float)(aB & 0xFFFFu); fb.y = (float)(aB >> 16);
    *reinterpret_cast<float2*>(&g_occ[c * N + iA0])      = fa;
    *reinterpret_cast<float2*>(&g_occ[c * N + iA0 + 64]) = fb;
}

// Generic-N fallback reduction (scalar, bounds-guarded).
__global__ __launch_bounds__(256)
void occ_reduce_generic(int N, int NP) {
    const int t = blockIdx.x * 256 + threadIdx.x;
    if (t >= NCELL * NP) return;
    const int c = t / NP;
    const int k = t - c * NP;
    unsigned sA = 0, sB = 0;
    #pragma unroll 8
    for (int sg = 0; sg < SEG; sg++) {
        const unsigned v = g_part[(sg * NCELL + c) * NP + k];
        sA += v & 0xFFu;
        sB += (v >> 8) & 0xFFu;
    }
    const int iA = (k >> 6) * 128 + (k & 63);
    const int iB = iA + 64;
    if (iA < N) g_occ[c * N + iA] = (float)sA;
    if (iB < N) g_occ[c * N + iB] = (float)sB;
}

// [N,36] x [36,128] GEMM with smem-staged W and broadcast occ reads.
// BI=16 -> 512 blocks: latency hiding via block count.
__global__ __launch_bounds__(256)
void occ_gemm_kernel(const float2* __restrict__ obs,
                     const float*  __restrict__ W,
                     const float*  __restrict__ b,
                     float*        __restrict__ out, int N) {
    __shared__ float sW[HID * 37];                   // stride 37: 5h+c mod 32 conflict-free
    __shared__ __align__(16) float occ_s[BI][40];    // row stride 40: float4-aligned
    __shared__ float sself[BI];

    const int tid = threadIdx.x;
    const int i0  = blockIdx.x * BI;

    // Stage W coalesced.
    for (int idx = tid; idx < HID * NCELL; idx += 256) {
        const int h = idx / NCELL;
        sW[h * 37 + (idx - h * NCELL)] = W[idx];
    }
    // Load occ tile (coalesced along i from the [cell][i] layout).
    for (int idx = tid; idx < NCELL * BI; idx += 256) {
        const int c = idx >> 4, l = idx & (BI - 1);
        const int i = i0 + l;
        occ_s[l][c] = (i < N) ? g_occ[c * N + i] : 0.f;
    }
    if (tid < BI) {
        const int i = i0 + tid;
        float v = 0.f;
        if (i < N) {
            const float2 p = obs[i];
            if (!isnan(p.x) && !isnan(p.y)) v = 1.f;
        }
        sself[tid] = v;
    }
    __syncthreads();

    const int h = tid & (HID - 1);
    float w[NCELL];
    #pragma unroll
    for (int c = 0; c < NCELL; c++) w[c] = sW[h * 37 + c];
    const float bias = b[h];

    const int il0 = (tid >> 7) * (BI / 2);
    #pragma unroll
    for (int r = 0; r < BI / 2; r++) {
        const int il = il0 + r;
        const int i  = i0 + il;
        if (i >= N) break;
        // Self-pair was counted at cell 21 iff agent i is finite; remove it.
        float acc = fmaf(-sself[il], w[21], bias);
        const float4* row = (const float4*)&occ_s[il][0];
        #pragma unroll
        for (int c4 = 0; c4 < 9; c4++) {
            const float4 v = row[c4];     // broadcast LDS.128
            acc = fmaf(v.x, w[c4 * 4 + 0], acc);
            acc = fmaf(v.y, w[c4 * 4 + 1], acc);
            acc = fmaf(v.z, w[c4 * 4 + 2], acc);
            acc = fmaf(v.w, w[c4 * 4 + 3], acc);
        }
        out[i * HID + h] = acc;
    }
}

extern "C" void kernel_launch(void* const* d_in, const int* in_sizes, int n_in,
                              void* d_out, int out_size) {
    const float2* obs = (const float2*)d_in[0];
    const float*  W   = (const float*)d_in[1];
    const float*  b   = (const float*)d_in[2];
    float*        out = (float*)d_out;
    const int N  = in_sizes[0] / 2;
    const int GX = (N + APB - 1) / APB;
    const int NP = GX * NT;                // pair slots

    dim3 g1(GX, SEG);
    if (N == MAXN) occ_pair_kernel<true><<<g1, NT>>>(obs, N, NP);
    else           occ_pair_kernel<false><<<g1, NT>>>(obs, N, NP);

    if ((N & 127) == 0) {
        const int rthreads = NCELL * (NP >> 1);
        occ_reduce_kernel<<<(rthreads + 127) / 128, 128>>>(N, NP);
    } else {
        const int rthreads = NCELL * NP;
        occ_reduce_generic<<<(rthreads + 255) / 256, 256>>>(N, NP);
    }
    occ_gemm_kernel<<<(N + BI - 1) / BI, 256>>>(obs, W, b, out, N);
}

// round 14
// speedup vs baseline: 1.1437x; 1.0504x over previous
#include <cuda_runtime.h>
#include <math.h>

#define GN     6
#define NROW   37      // 36 cells + 1 trash row
#define NCELL  36
#define HID    128
#define NT     64      // threads per block (pair kernel)
#define APB    (2*NT)  // agents per block = 128 (2 per thread)
#define SEG    64      // j-segments -> grid 4096 when N=8192
#define TJ     128     // j tile size; counts per segment <= 128 -> fit in u8
#define MAXN   8192
#define BI     16      // rows per block in GEMM kernel (512 blocks at N=8192)

// Packed partials: [seg][cell][k] u16 = (countA:u8) | (countB:u8 << 8),
// where pair k -> agents iA = (k>>6)*128 + (k&63), iB = iA + 64.
__device__ unsigned short g_part[SEG * NCELL * (MAXN / 2)];
// Reduced occupancy, transposed float: [cell][i]
__device__ float g_occ[NCELL * MAXN];
// W transposed: [cell][h] -> gemm reads are coalesced broadcasts (L1/L2 hits)
__device__ float g_Wt[NCELL * HID];

__device__ __forceinline__ unsigned long long addf32x2(unsigned long long a,
                                                       unsigned long long b) {
    unsigned long long r;
    asm("add.rn.f32x2 %0, %1, %2;" : "=l"(r) : "l"(a), "l"(b));
    return r;
}
__device__ __forceinline__ unsigned long long packf2(float lo, float hi) {
    unsigned long long r;
    asm("mov.b64 %0, {%1, %2};" : "=l"(r) : "f"(lo), "f"(hi));
    return r;
}

// pj holds packed (2xj+3, 2yj+3); ni holds packed (-2xi, -2yi); one FADD2 joins
// them (per-lane RN identical to scalar FADD). Validity: umax(ix,iy) < 6 covers
// negatives (unsigned-huge), >=6, and saturated F2I from the +1e30 sentinels;
// invalid -> trash row 36 via one SEL. Histogram u32, conflict-free
// (bank = tid%32): agent A at bit 0, agent B at bit 16; counts <= 128.
__device__ __forceinline__ void bump(unsigned* occ, int tid,
                                     unsigned long long pj, unsigned long long ni,
                                     unsigned inc) {
    const unsigned long long r = addf32x2(pj, ni);
    float fx, fy;
    asm("mov.b64 {%0, %1}, %2;" : "=f"(fx), "=f"(fy) : "l"(r));
    unsigned ix = (unsigned)__float2int_rd(fx);
    unsigned iy = (unsigned)__float2int_rd(fy);
    unsigned m  = umax(ix, iy);
    unsigned cell = ix * GN + iy;
    cell = (m < (unsigned)GN) ? cell : (unsigned)NCELL;
    occ[cell * NT + tid] += inc;
}

template<bool EXACT>
__global__ __launch_bounds__(NT, 20)
void occ_pair_kernel(const float2* __restrict__ obs, int N, int NP) {
    __shared__ __align__(16) float2 tile[TJ];    // holds (2*xj+3, 2*yj+3)
    __shared__ unsigned occ[NROW * NT];

    const int tid = threadIdx.x;
    const int iA  = blockIdx.x * APB + tid;
    const int iB  = iA + NT;
    const int seg = blockIdx.y;
    const int JS  = EXACT ? (MAXN / SEG) : ((N + SEG - 1) / SEG);
    const int j0  = seg * JS;
    const int j1  = EXACT ? (j0 + JS) : min(j0 + JS, N);

    // Hold packed -2*x_i (exact: *2 exact, negate exact). Invalid -> +1e30.
    float nxA = 1e30f, nyA = 1e30f, nxB = 1e30f, nyB = 1e30f;
    if (iA < N) {
        float2 p = obs[iA];
        if (!isnan(p.x) && !isnan(p.y)) { nxA = -2.0f * p.x; nyA = -2.0f * p.y; }
    }
    if (iB < N) {
        float2 p = obs[iB];
        if (!isnan(p.x) && !isnan(p.y)) { nxB = -2.0f * p.x; nyB = -2.0f * p.y; }
    }
    const unsigned long long nA = packf2(nxA, nyA);
    const unsigned long long nB = packf2(nxB, nyB);

    #pragma unroll
    for (int c = 0; c < NROW; c++) occ[c * NT + tid] = 0;
    __syncthreads();

    for (int jb = j0; jb < j1; jb += TJ) {
        const int nj = EXACT ? TJ : min(TJ, j1 - jb);
        for (int t = tid; t < nj; t += NT) {
            float2 p = obs[jb + t];
            float2 v;
            if (isnan(p.x) || isnan(p.y)) { v.x = 1e30f; v.y = 1e30f; }
            else { v.x = fmaf(p.x, 2.0f, 3.0f); v.y = fmaf(p.y, 2.0f, 3.0f); }
            tile[t] = v;
        }
        __syncthreads();

        // Two packed j's per LDS.128 broadcast; one FADD2 per pair.
        const ulonglong2* t2 = (const ulonglong2*)tile;
        const int nj2 = nj >> 1;
        #pragma unroll 4
        for (int jj = 0; jj < nj2; jj++) {
            const ulonglong2 q = t2[jj];
            bump(occ, tid, q.x, nA, 1u);
            bump(occ, tid, q.x, nB, 1u << 16);
            bump(occ, tid, q.y, nA, 1u);
            bump(occ, tid, q.y, nB, 1u << 16);
        }
        if (!EXACT && (nj & 1)) {
            const unsigned long long q =
                *reinterpret_cast<const unsigned long long*>(&tile[nj - 1]);
            bump(occ, tid, q, nA, 1u);
            bump(occ, tid, q, nB, 1u << 16);
        }
        __syncthreads();
    }

    // Store 36 real cells packed: (A count u8) | (B count u8 << 8). OOB agents
    // contributed only to the trash row, so their real cells are 0 -> safe.
    const int k = blockIdx.x * NT + tid;
    #pragma unroll
    for (int c = 0; c < NCELL; c++) {
        const unsigned v = occ[c * NT + tid];
        g_part[(seg * NCELL + c) * NP + k] =
            (unsigned short)((v & 0xFFu) | ((v >> 8) & 0xFF00u));
    }
}

// Vector reduction (N % 128 == 0): one thread per (cell, 2 pair-slots).
// 73728 threads at N=8192 -> latency fully hidden; u32 load = 2 packed slots.
// Block 0 additionally transposes W into g_Wt for the GEMM.
__global__ __launch_bounds__(128)
void occ_reduce_kernel(const float* __restrict__ W, int N, int NP) {
    if (blockIdx.x == 0) {
        const int h = threadIdx.x;                   // 128 threads = 128 features
        #pragma unroll
        for (int c = 0; c < NCELL; c++)
            g_Wt[c * HID + h] = W[h * NCELL + c];
    }

    const int nK2 = NP >> 1;
    const int t   = blockIdx.x * 128 + threadIdx.x;
    if (t >= NCELL * nK2) return;
    const int c  = t / nK2;
    const int k0 = (t - c * nK2) * 2;

    unsigned aA = 0u, aB = 0u;
    const unsigned* base = reinterpret_cast<const unsigned*>(g_part) + (c * NP + k0) / 2;
    #pragma unroll 16
    for (int sg = 0; sg < SEG; sg++) {
        const unsigned v = base[sg * (NCELL * NP / 2)];
        aA = __vadd2(aA, v & 0x00FF00FFu);
        aB = __vadd2(aB, (v >> 8) & 0x00FF00FFu);
    }
    // Agents: iA0, iA0+1 (consecutive) and iA0+64, iA0+65.
    const int iA0 = (k0 >> 6) * 128 + (k0 & 63);
    float2 fa, fb;
    fa.x = (float)(aA & 0xFFFFu); fa.y = (float)(aA >> 16);
    fb.x = (float)(aB & 0xFFFFu); fb.y = (float)(aB >> 16);
    *reinterpret_cast<float2*>(&g_occ[c * N + iA0])      = fa;
    *reinterpret_cast<float2*>(&g_occ[c * N + iA0 + 64]) = fb;
}

// Generic-N fallback reduction (scalar, bounds-guarded).
__global__ __launch_bounds__(256)
void occ_reduce_generic(const float* __restrict__ W, int N, int NP) {
    if (blockIdx.x == 0 && threadIdx.x < HID) {
        const int h = threadIdx.x;
        #pragma unroll
        for (int c = 0; c < NCELL; c++)
            g_Wt[c * HID + h] = W[h * NCELL + c];
    }
    const int t = blockIdx.x * 256 + threadIdx.x;
    if (t >= NCELL * NP) return;
    const int c = t / NP;
    const int k = t - c * NP;
    unsigned sA = 0, sB = 0;
    #pragma unroll 8
    for (int sg = 0; sg < SEG; sg++) {
        const unsigned v = g_part[(sg * NCELL + c) * NP + k];
        sA += v & 0xFFu;
        sB += (v >> 8) & 0xFFu;
    }
    const int iA = (k >> 6) * 128 + (k & 63);
    const int iB = iA + 64;
    if (iA < N) g_occ[c * N + iA] = (float)sA;
    if (iB < N) g_occ[c * N + iB] = (float)sB;
}

// [N,36] x [36,128] GEMM. W comes pre-transposed (g_Wt[c][h]) -> per-thread
// w-loads are coalesced L1/L2-hit broadcasts; no per-block smem staging.
__global__ __launch_bounds__(256)
void occ_gemm_kernel(const float2* __restrict__ obs,
                     const float*  __restrict__ b,
                     float*        __restrict__ out, int N) {
    __shared__ __align__(16) float occ_s[BI][40];    // row stride 40: float4-aligned
    __shared__ float sself[BI];

    const int tid = threadIdx.x;
    const int i0  = blockIdx.x * BI;

    // Load occ tile (coalesced along i from the [cell][i] layout).
    for (int idx = tid; idx < NCELL * BI; idx += 256) {
        const int c = idx >> 4, l = idx & (BI - 1);
        const int i = i0 + l;
        occ_s[l][c] = (i < N) ? g_occ[c * N + i] : 0.f;
    }
    if (tid < BI) {
        const int i = i0 + tid;
        float v = 0.f;
        if (i < N) {
            const float2 p = obs[i];
            if (!isnan(p.x) && !isnan(p.y)) v = 1.f;
        }
        sself[tid] = v;
    }

    const int h = tid & (HID - 1);
    float w[NCELL];
    #pragma unroll
    for (int c = 0; c < NCELL; c++) w[c] = g_Wt[c * HID + h];
    const float bias = b[h];
    __syncthreads();

    const int il0 = (tid >> 7) * (BI / 2);
    #pragma unroll
    for (int r = 0; r < BI / 2; r++) {
        const int il = il0 + r;
        const int i  = i0 + il;
        if (i >= N) break;
        // Self-pair was counted at cell 21 iff agent i is finite; remove it.
        float acc = fmaf(-sself[il], w[21], bias);
        const float4* row = (const float4*)&occ_s[il][0];
        #pragma unroll
        for (int c4 = 0; c4 < 9; c4++) {
            const float4 v = row[c4];     // broadcast LDS.128
            acc = fmaf(v.x, w[c4 * 4 + 0], acc);
            acc = fmaf(v.y, w[c4 * 4 + 1], acc);
            acc = fmaf(v.z, w[c4 * 4 + 2], acc);
            acc = fmaf(v.w, w[c4 * 4 + 3], acc);
        }
        out[i * HID + h] = acc;
    }
}

extern "C" void kernel_launch(void* const* d_in, const int* in_sizes, int n_in,
                              void* d_out, int out_size) {
    const float2* obs = (const float2*)d_in[0];
    const float*  W   = (const float*)d_in[1];
    const float*  b   = (const float*)d_in[2];
    float*        out = (float*)d_out;
    const int N  = in_sizes[0] / 2;
    const int GX = (N + APB - 1) / APB;
    const int NP = GX * NT;                // pair slots

    dim3 g1(GX, SEG);
    if (N == MAXN) occ_pair_kernel<true><<<g1, NT>>>(obs, N, NP);
    else           occ_pair_kernel<false><<<g1, NT>>>(obs, N, NP);

    if ((N & 127) == 0) {
        const int rthreads = NCELL * (NP >> 1);
        occ_reduce_kernel<<<(rthreads + 127) / 128, 128>>>(W, N, NP);
    } else {
        const int rthreads = NCELL * NP;
        occ_reduce_generic<<<(rthreads + 255) / 256, 256>>>(W, N, NP);
    }
    occ_gemm_kernel<<<(N + BI - 1) / BI, 256>>>(obs, b, out, N);
}

// round 17
// speedup vs baseline: 1.3162x; 1.1508x over previous
#include <cuda_runtime.h>
#include <math.h>

#define GN     6
#define GC     7       // clamped grid side (row/col 6 = trash)
#define NROW   (GC*GC) // 49 histogram rows
#define NCELL  36
#define HID    128
#define NT     64      // threads per block (pair kernel)
#define APB    (2*NT)  // agents per block = 128 (2 per thread)
#define SEG    64      // j-segments -> grid 4096 when N=8192
#define TJ     128     // j tile size; counts per segment <= 128 -> fit in u8
#define MAXN   8192
#define BI     16      // rows per block in GEMM kernel (512 blocks at N=8192)

#define MAGIC     12582912.0f   // 1.5 * 2^23: floats in [2^23,2^24) have ulp 1
#define MAGIC_U   0x4B400000u   // bit pattern of 12582912.0f
#define SENT      1e30f         // sentinel: x ~ 1e30/2e30 -> index huge -> clamp

// Packed partials: [seg][cell][k] u16 = (countA:u8) | (countB:u8 << 8),
// where pair k -> agents iA = (k>>6)*128 + (k&63), iB = iA + 64.
__device__ unsigned short g_part[SEG * NCELL * (MAXN / 2)];
// Reduced occupancy, transposed float: [cell][i]
__device__ float g_occ[NCELL * MAXN];
// W transposed: [cell][h] -> gemm reads are coalesced broadcasts (L1/L2 hits)
__device__ float g_Wt[NCELL * HID];

__device__ __forceinline__ unsigned long long addf32x2(unsigned long long a,
                                                       unsigned long long b) {
    unsigned long long r;
    asm("add.rn.f32x2 %0, %1, %2;" : "=l"(r) : "l"(a), "l"(b));
    return r;
}
__device__ __forceinline__ unsigned long long packf2(float lo, float hi) {
    unsigned long long r;
    asm("mov.b64 %0, {%1, %2};" : "=l"(r) : "f"(lo), "f"(hi));
    return r;
}

// pj holds packed (2xj+3, 2yj+3); ni holds packed (-2xi, -2yi); one FADD2
// joins them -> x is bit-identical to the R14-verified grid coordinate.
// Exact floor WITHOUT the cvt pipe: __fadd_rd(x, MAGIC) (FADD.RM, fma pipe).
// For |x| < 2^22 the sum sits where ulp=1, so round-down gives exactly
// MAGIC + floor(x): bits = MAGIC_U + floor(x), one IADD recovers the index.
// Invalid (negative -> bit-wrap below MAGIC_U, >=6, 1e30 sentinels) all give
// index >= 6 -> umin clamps into the 7x7 grid's trash row/col. Branchless.
// Histogram u32, conflict-free (bank = tid%32): agent A at bit 0, agent B at
// bit 16; counts <= TJ=128 so the fields never interact.
__device__ __forceinline__ void bump(unsigned* occ, int tid,
                                     unsigned long long pj, unsigned long long ni,
                                     unsigned inc) {
    const unsigned long long r = addf32x2(pj, ni);
    float fx, fy;
    asm("mov.b64 {%0, %1}, %2;" : "=f"(fx), "=f"(fy) : "l"(r));
    unsigned ix = umin(__float_as_uint(__fadd_rd(fx, MAGIC)) - MAGIC_U, (unsigned)(GC - 1));
    unsigned iy = umin(__float_as_uint(__fadd_rd(fy, MAGIC)) - MAGIC_U, (unsigned)(GC - 1));
    occ[(ix * GC + iy) * NT + tid] += inc;
}

template<bool EXACT>
__global__ __launch_bounds__(NT, 16)
void occ_pair_kernel(const float2* __restrict__ obs, int N, int NP) {
    __shared__ __align__(16) float2 tile[TJ];    // holds (2*xj+3, 2*yj+3)
    __shared__ unsigned occ[NROW * NT];

    const int tid = threadIdx.x;
    const int iA  = blockIdx.x * APB + tid;
    const int iB  = iA + NT;
    const int seg = blockIdx.y;
    const int JS  = EXACT ? (MAXN / SEG) : ((N + SEG - 1) / SEG);
    const int j0  = seg * JS;
    const int j1  = EXACT ? (j0 + JS) : min(j0 + JS, N);

    // Hold packed -2*x_i (exact: *2 exact, negate exact). Invalid -> SENT.
    float nxA = SENT, nyA = SENT, nxB = SENT, nyB = SENT;
    if (iA < N) {
        float2 p = obs[iA];
        if (!isnan(p.x) && !isnan(p.y)) { nxA = -2.0f * p.x; nyA = -2.0f * p.y; }
    }
    if (iB < N) {
        float2 p = obs[iB];
        if (!isnan(p.x) && !isnan(p.y)) { nxB = -2.0f * p.x; nyB = -2.0f * p.y; }
    }
    const unsigned long long nA = packf2(nxA, nyA);
    const unsigned long long nB = packf2(nxB, nyB);

    #pragma unroll
    for (int c = 0; c < NROW; c++) occ[c * NT + tid] = 0;
    __syncthreads();

    for (int jb = j0; jb < j1; jb += TJ) {
        const int nj = EXACT ? TJ : min(TJ, j1 - jb);
        for (int t = tid; t < nj; t += NT) {
            float2 p = obs[jb + t];
            float2 v;
            if (isnan(p.x) || isnan(p.y)) { v.x = SENT; v.y = SENT; }
            else { v.x = fmaf(p.x, 2.0f, 3.0f); v.y = fmaf(p.y, 2.0f, 3.0f); }
            tile[t] = v;
        }
        __syncthreads();

        // Two packed j's per LDS.128 broadcast; FADD2 + 2 FADD.RM per pair.
        const ulonglong2* t2 = (const ulonglong2*)tile;
        const int nj2 = nj >> 1;
        #pragma unroll 4
        for (int jj = 0; jj < nj2; jj++) {
            const ulonglong2 q = t2[jj];
            bump(occ, tid, q.x, nA, 1u);
            bump(occ, tid, q.x, nB, 1u << 16);
            bump(occ, tid, q.y, nA, 1u);
            bump(occ, tid, q.y, nB, 1u << 16);
        }
        if (!EXACT && (nj & 1)) {
            const unsigned long long q =
                *reinterpret_cast<const unsigned long long*>(&tile[nj - 1]);
            bump(occ, tid, q, nA, 1u);
            bump(occ, tid, q, nB, 1u << 16);
        }
        __syncthreads();
    }

    // Store the 36 real cells packed (skip clamp row/col 6). OOB agents
    // contributed only to clamp rows, so their real cells are 0 -> safe.
    const int k = blockIdx.x * NT + tid;
    #pragma unroll
    for (int c = 0; c < NCELL; c++) {
        const int row = (c / GN) * GC + (c % GN);
        const unsigned v = occ[row * NT + tid];
        g_part[(seg * NCELL + c) * NP + k] =
            (unsigned short)((v & 0xFFu) | ((v >> 8) & 0xFF00u));
    }
}

// Vector reduction (N % 128 == 0): one thread per (cell, 2 pair-slots).
// 73728 threads at N=8192 -> latency fully hidden; u32 load = 2 packed slots.
// Block 0 additionally transposes W into g_Wt for the GEMM.
__global__ __launch_bounds__(128)
void occ_reduce_kernel(const float* __restrict__ W, int N, int NP) {
    if (blockIdx.x == 0) {
        const int h = threadIdx.x;                   // 128 threads = 128 features
        #pragma unroll
        for (int c = 0; c < NCELL; c++)
            g_Wt[c * HID + h] = W[h * NCELL + c];
    }

    const int nK2 = NP >> 1;
    const int t   = blockIdx.x * 128 + threadIdx.x;
    if (t >= NCELL * nK2) return;
    const int c  = t / nK2;
    const int k0 = (t - c * nK2) * 2;

    unsigned aA = 0u, aB = 0u;
    const unsigned* base = reinterpret_cast<const unsigned*>(g_part) + (c * NP + k0) / 2;
    #pragma unroll 16
    for (int sg = 0; sg < SEG; sg++) {
        const unsigned v = base[sg * (NCELL * NP / 2)];
        aA = __vadd2(aA, v & 0x00FF00FFu);
        aB = __vadd2(aB, (v >> 8) & 0x00FF00FFu);
    }
    // Agents: iA0, iA0+1 (consecutive) and iA0+64, iA0+65.
    const int iA0 = (k0 >> 6) * 128 + (k0 & 63);
    float2 fa, fb;
    fa.x = (float)(aA & 0xFFFFu); fa.y = (float)(aA >> 16);
    fb.x = (float)(aB & 0xFFFFu); fb.y = (float)(aB >> 16);
    *reinterpret_cast<float2*>(&g_occ[c * N + iA0])      = fa;
    *reinterpret_cast<float2*>(&g_occ[c * N + iA0 + 64]) = fb;
}

// Generic-N fallback reduction (scalar, bounds-guarded).
__global__ __launch_bounds__(256)
void occ_reduce_generic(const float* __restrict__ W, int N, int NP) {
    if (blockIdx.x == 0 && threadIdx.x < HID) {
        const int h = threadIdx.x;
        #pragma unroll
        for (int c = 0; c < NCELL; c++)
            g_Wt[c * HID + h] = W[h * NCELL + c];
    }
    const int t = blockIdx.x * 256 + threadIdx.x;
    if (t >= NCELL * NP) return;
    const int c = t / NP;
    const int k = t - c * NP;
    unsigned sA = 0, sB = 0;
    #pragma unroll 8
    for (int sg = 0; sg < SEG; sg++) {
        const unsigned v = g_part[(sg * NCELL + c) * NP + k];
        sA += v & 0xFFu;
        sB += (v >> 8) & 0xFFu;
    }
    const int iA = (k >> 6) * 128 + (k & 63);
    const int iB = iA + 64;
    if (iA < N) g_occ[c * N + iA] = (float)sA;
    if (iB < N) g_occ[c * N + iB] = (float)sB;
}

// [N,36] x [36,128] GEMM. W comes pre-transposed (g_Wt[c][h]) -> per-thread
// w-loads are coalesced L1/L2-hit broadcasts; no per-block smem staging.
__global__ __launch_bounds__(256)
void occ_gemm_kernel(const float2* __restrict__ obs,
                     const float*  __restrict__ b,
                     float*        __restrict__ out, int N) {
    __shared__ __align__(16) float occ_s[BI][40];    // row stride 40: float4-aligned
    __shared__ float sself[BI];

    const int tid = threadIdx.x;
    const int i0  = blockIdx.x * BI;

    // Load occ tile (coalesced along i from the [cell][i] layout).
    for (int idx = tid; idx < NCELL * BI; idx += 256) {
        const int c = idx >> 4, l = idx & (BI - 1);
        const int i = i0 + l;
        occ_s[l][c] = (i < N) ? g_occ[c * N + i] : 0.f;
    }
    if (tid < BI) {
        const int i = i0 + tid;
        float v = 0.f;
        if (i < N) {
            const float2 p = obs[i];
            if (!isnan(p.x) && !isnan(p.y)) v = 1.f;
        }
        sself[tid] = v;
    }

    const int h = tid & (HID - 1);
    float w[NCELL];
    #pragma unroll
    for (int c = 0; c < NCELL; c++) w[c] = g_Wt[c * HID + h];
    const float bias = b[h];
    __syncthreads();

    const int il0 = (tid >> 7) * (BI / 2);
    #pragma unroll
    for (int r = 0; r < BI / 2; r++) {
        const int il = il0 + r;
        const int i  = i0 + il;
        if (i >= N) break;
        // Self-pair was counted at cell 21 iff agent i is finite; remove it.
        float acc = fmaf(-sself[il], w[21], bias);
        const float4* row = (const float4*)&occ_s[il][0];
        #pragma unroll
        for (int c4 = 0; c4 < 9; c4++) {
            const float4 v = row[c4];     // broadcast LDS.128
            acc = fmaf(v.x, w[c4 * 4 + 0], acc);
            acc = fmaf(v.y, w[c4 * 4 + 1], acc);
            acc = fmaf(v.z, w[c4 * 4 + 2], acc);
            acc = fmaf(v.w, w[c4 * 4 + 3], acc);
        }
        out[i * HID + h] = acc;
    }
}

extern "C" void kernel_launch(void* const* d_in, const int* in_sizes, int n_in,
                              void* d_out, int out_size) {
    const float2* obs = (const float2*)d_in[0];
    const float*  W   = (const float*)d_in[1];
    const float*  b   = (const float*)d_in[2];
    float*        out = (float*)d_out;
    const int N  = in_sizes[0] / 2;
    const int GX = (N + APB - 1) / APB;
    const int NP = GX * NT;                // pair slots

    dim3 g1(GX, SEG);
    if (N == MAXN) occ_pair_kernel<true><<<g1, NT>>>(obs, N, NP);
    else           occ_pair_kernel<false><<<g1, NT>>>(obs, N, NP);

    if ((N & 127) == 0) {
        const int rthreads = NCELL * (NP >> 1);
        occ_reduce_kernel<<<(rthreads + 127) / 128, 128>>>(W, N, NP);
    } else {
        const int rthreads = NCELL * NP;
        occ_reduce_generic<<<(rthreads + 255) / 256, 256>>>(W, N, NP);
    }
    occ_gemm_kernel<<<(N + BI - 1) / BI, 256>>>(obs, b, out, N);
}